// round 16
// baseline (speedup 1.0000x reference)
#include <cuda_runtime.h>
#include <cstdint>

// MemoryReader attention — tensor-pipe logits (bf16 3-split) + tf32 readout.
// R16 = R12's minimal 4-barrier skeleton + exactly two access-pattern fixes:
//   (1) K pitch 72 (R12's pitch-68 logit frags were 2-way bank-conflicted)
//   (2) Q fragments lifted to registers (logit A-frag LDS stream removed)
// No K prefetch staging, no overlay, no mbarriers (R13-R15 restructures all
// measured negative). 2 CTAs/SM via channel split.
//   B=16, CK=64, CV=512, N=3136, 64 queries/CTA, 64-key tiles.

#define Bsz     16
#define CKc     64
#define CVc     512
#define NPIX    3136
#define MQ      64
#define NT      64
#define THREADS 256
#define NTILES  49
#define CVH     256

#define KP 72    // K hi/lo (+Q staging) pitch: frag banks (8tq+g) bijective
#define P  68    // Et / V pitch: frag banks (4g+tq) bijective

// smem word offsets (per CTA: 26496 words = 105984 B; x2 CTAs = 211968 B)
#define KH_OFF 0                 // Kh [32cp][KP]  (Q staged here in prologue)
#define KL_OFF (KH_OFF + 32*KP)  // Kl [32cp][KP]
#define ET_OFF (KL_OFF + 32*KP)  // Et [64q][P] tf32 bits
#define VS_OFF (ET_OFF + MQ*P)   // V  [256ch][P] raw fp32
#define S2_OFF (VS_OFF + CVH*P)
#define DN_OFF (S2_OFF + NT)
#define SMEM_W (DN_OFF + MQ)

__device__ __forceinline__ float tf32r(float x) {
    uint32_t u; asm("cvt.rna.tf32.f32 %0, %1;" : "=r"(u) : "f"(x));
    return __uint_as_float(u);
}
__device__ __forceinline__ uint32_t bf16x2p(float odd, float even) {
    uint32_t r;
    asm("cvt.rn.bf16x2.f32 %0, %1, %2;" : "=r"(r) : "f"(odd), "f"(even));
    return r;
}
__device__ __forceinline__ float bfLO(uint32_t w) { return __uint_as_float(w << 16); }
__device__ __forceinline__ float bfHI(uint32_t w) { return __uint_as_float(w & 0xffff0000u); }

__device__ __forceinline__ void mma_tf32(float d[4], const uint32_t a[4], const uint32_t b[2]) {
    asm volatile(
        "mma.sync.aligned.m16n8k8.row.col.f32.tf32.tf32.f32 "
        "{%0,%1,%2,%3}, {%4,%5,%6,%7}, {%8,%9}, {%0,%1,%2,%3};"
        : "+f"(d[0]), "+f"(d[1]), "+f"(d[2]), "+f"(d[3])
        : "r"(a[0]), "r"(a[1]), "r"(a[2]), "r"(a[3]), "r"(b[0]), "r"(b[1]));
}
__device__ __forceinline__ void mma_bf16(float d[4], const uint32_t a[4], const uint32_t b[2]) {
    asm volatile(
        "mma.sync.aligned.m16n8k16.row.col.f32.bf16.bf16.f32 "
        "{%0,%1,%2,%3}, {%4,%5,%6,%7}, {%8,%9}, {%0,%1,%2,%3};"
        : "+f"(d[0]), "+f"(d[1]), "+f"(d[2]), "+f"(d[3])
        : "r"(a[0]), "r"(a[1]), "r"(a[2]), "r"(a[3]), "r"(b[0]), "r"(b[1]));
}
__device__ __forceinline__ void cpasync16(uint32_t dst, const void* src) {
    asm volatile("cp.async.cg.shared.global [%0], [%1], 16;" :: "r"(dst), "l"(src));
}

__global__ __launch_bounds__(THREADS, 2)
void mr_attn_kernel(const float* __restrict__ mk, const float* __restrict__ qk,
                    const float* __restrict__ mv, float* __restrict__ out)
{
    extern __shared__ float sm[];
    float* Et = sm + ET_OFF;
    float* S2 = sm + S2_OFF;
    float* Dn = sm + DN_OFF;
    uint32_t* KhW = (uint32_t*)(sm + KH_OFF);
    uint32_t* KlW = (uint32_t*)(sm + KL_OFF);
    uint32_t* VsW = (uint32_t*)(sm + VS_OFF);

    uint32_t sbase;
    asm("{ .reg .u64 t; cvta.to.shared.u64 t, %1; cvt.u32.u64 %0, t; }"
        : "=r"(sbase) : "l"(sm));

    const int b    = blockIdx.y;
    const int m0   = blockIdx.x * MQ;
    const int zc   = blockIdx.z * CVH;
    const int tid  = threadIdx.x;
    const int wid  = tid >> 5;
    const int lane = tid & 31;
    const int g    = lane >> 2;
    const int tq   = lane & 3;

    const float* qb = qk + (size_t)b * CKc * NPIX + m0;
    const float* kb = mk + (size_t)b * CKc * NPIX;
    const float* vb = mv + ((size_t)b * CVc + zc) * NPIX;

    const int ch0 = wid * 32;        // readout channel slab
    const int wq  = wid & 3;         // logit q m-tile (16q)
    const int wk  = wid >> 2;        // logit k half (32k)
    const int q0  = wq * 16;
    const int kh0 = wk * 32;

    // ---------- prologue: stage Q hi/lo into K region, lift to registers ----------
    #pragma unroll
    for (int it = 0; it < 2; ++it) {
        int slot = it * THREADS + tid;
        int cp = slot >> 4, m4 = slot & 15;
        const float* q0p = qb + (2 * cp) * NPIX + 4 * m4;
        float4 qe = *(const float4*)(q0p);
        float4 qo = *(const float4*)(q0p + NPIX);
        float xe[4] = {qe.x, qe.y, qe.z, qe.w};
        float xo[4] = {qo.x, qo.y, qo.z, qo.w};
        uint32_t hv[4], lv[4];
        #pragma unroll
        for (int r = 0; r < 4; ++r) {
            uint32_t h = bf16x2p(xo[r], xe[r]);
            hv[r] = h;
            lv[r] = bf16x2p(xo[r] - bfHI(h), xe[r] - bfLO(h));
        }
        *(uint4*)(KhW + cp * KP + 4 * m4) = *(uint4*)hv;
        *(uint4*)(KlW + cp * KP + 4 * m4) = *(uint4*)lv;
    }
    if (tid < MQ) Dn[tid] = 0.f;
    __syncthreads();

    uint32_t qh_r[4][4], ql_r[4][4];
    #pragma unroll
    for (int cs = 0; cs < 4; ++cs) {
        const int cb = cs * 8;
        qh_r[cs][0] = KhW[(cb + tq) * KP + q0 + g];
        qh_r[cs][1] = KhW[(cb + tq) * KP + q0 + g + 8];
        qh_r[cs][2] = KhW[(cb + tq + 4) * KP + q0 + g];
        qh_r[cs][3] = KhW[(cb + tq + 4) * KP + q0 + g + 8];
        ql_r[cs][0] = KlW[(cb + tq) * KP + q0 + g];
        ql_r[cs][1] = KlW[(cb + tq) * KP + q0 + g + 8];
        ql_r[cs][2] = KlW[(cb + tq + 4) * KP + q0 + g];
        ql_r[cs][3] = KlW[(cb + tq + 4) * KP + q0 + g + 8];
    }

    float d[2][8][4];
    #pragma unroll
    for (int i = 0; i < 2; ++i)
        #pragma unroll
        for (int j = 0; j < 8; ++j)
            #pragma unroll
            for (int r = 0; r < 4; ++r) d[i][j][r] = 0.f;

    // ---------- main loop (R12 skeleton: 4 barriers/tile) ----------
    #pragma unroll 1
    for (int t = 0; t < NTILES; ++t) {
        const int n0 = t * NT;
        __syncthreads();   // B1: readout(t-1) done (and Q lift at t=0); tiles reusable

        // V(t): cp.async raw fp32 (overlaps K convert + logit + exp)
        #pragma unroll
        for (int i = 0; i < 16; ++i) {
            int idx = i * THREADS + tid;
            int c = idx >> 4, n4 = idx & 15;
            cpasync16(sbase + (uint32_t)(VS_OFF + c * P + 4 * n4) * 4u,
                      vb + c * NPIX + n0 + 4 * n4);
        }
        asm volatile("cp.async.commit_group;" ::: "memory");

        // K(t): LDG -> bf16 hi/lo -> STS (pitch KP=72, conflict-free)
        #pragma unroll
        for (int it = 0; it < 2; ++it) {
            int slot = it * THREADS + tid;
            int cp = slot >> 4, n4 = slot & 15;
            const float* k0p = kb + (2 * cp) * NPIX + n0 + 4 * n4;
            float4 ke = *(const float4*)(k0p);
            float4 ko = *(const float4*)(k0p + NPIX);
            float xe[4] = {ke.x, ke.y, ke.z, ke.w};
            float xo[4] = {ko.x, ko.y, ko.z, ko.w};
            uint32_t hv[4], lv[4];
            #pragma unroll
            for (int r = 0; r < 4; ++r) {
                uint32_t h = bf16x2p(xo[r], xe[r]);
                hv[r] = h;
                lv[r] = bf16x2p(xo[r] - bfHI(h), xe[r] - bfLO(h));
            }
            *(uint4*)(KhW + cp * KP + 4 * n4) = *(uint4*)hv;
            *(uint4*)(KlW + cp * KP + 4 * n4) = *(uint4*)lv;
        }
        __syncthreads();   // B2: K(t) ready

        // ||k||^2 (warps 0-1); banks (8cp+lane) conflict-free
        if (tid < NT) {
            float s = 0.f;
            #pragma unroll
            for (int cp = 0; cp < 32; ++cp) {
                uint32_t wh = KhW[cp * KP + tid], wl = KlW[cp * KP + tid];
                float ke = bfLO(wh) + bfLO(wl);
                float ko = bfHI(wh) + bfHI(wl);
                s = fmaf(ke, ke, fmaf(ko, ko, s));
            }
            S2[tid] = s;
        }

        // Logit MMA: warp = 16q x 32k, 3x bf16-split; Q from registers,
        // K frags banks (8tq+g) bijective -> conflict-free
        float dl[4][4];
        #pragma unroll
        for (int j = 0; j < 4; ++j)
            #pragma unroll
            for (int r = 0; r < 4; ++r) dl[j][r] = 0.f;
        #pragma unroll
        for (int cs = 0; cs < 4; ++cs) {
            const int cb = cs * 8;
            #pragma unroll
            for (int j = 0; j < 4; ++j) {
                const int kk0 = kh0 + 8 * j;
                uint32_t bh[2], bl2[2];
                bh[0]  = KhW[(cb + tq) * KP + kk0 + g];
                bh[1]  = KhW[(cb + tq + 4) * KP + kk0 + g];
                bl2[0] = KlW[(cb + tq) * KP + kk0 + g];
                bl2[1] = KlW[(cb + tq + 4) * KP + kk0 + g];
                mma_bf16(dl[j], qh_r[cs], bh);
                mma_bf16(dl[j], qh_r[cs], bl2);
                mma_bf16(dl[j], ql_r[cs], bh);
            }
        }
        __syncthreads();   // B3: S2 visible to all

        // exp -> Et[q][k] (tf32 bits) + denominator
        {
            const float C1 = 0.125f * 1.4426950408889634f;   // log2(e)/8
            float pA = 0.f, pB = 0.f;
            #pragma unroll
            for (int j = 0; j < 4; ++j) {
                const int kk = kh0 + 8 * j + 2 * tq;
                float2 s2v = *(const float2*)(S2 + kk);
                float sbx = s2v.x * C1, sby = s2v.y * C1;
                float e0 = exp2f(fmaf(dl[j][0], 2.f * C1, -sbx));
                float e1 = exp2f(fmaf(dl[j][1], 2.f * C1, -sby));
                float e2 = exp2f(fmaf(dl[j][2], 2.f * C1, -sbx));
                float e3 = exp2f(fmaf(dl[j][3], 2.f * C1, -sby));
                *(float2*)(Et + (q0 + g) * P + kk)     = make_float2(tf32r(e0), tf32r(e1));
                *(float2*)(Et + (q0 + g + 8) * P + kk) = make_float2(tf32r(e2), tf32r(e3));
                pA += e0 + e1;
                pB += e2 + e3;
            }
            pA += __shfl_xor_sync(0xffffffffu, pA, 1);
            pA += __shfl_xor_sync(0xffffffffu, pA, 2);
            pB += __shfl_xor_sync(0xffffffffu, pB, 1);
            pB += __shfl_xor_sync(0xffffffffu, pB, 2);
            if (tq == 0) {
                atomicAdd(&Dn[q0 + g], pA);
                atomicAdd(&Dn[q0 + g + 8], pB);
            }
        }
        asm volatile("cp.async.wait_group 0;" ::: "memory");
        __syncthreads();   // B4: Et complete + V(t) visible

        // Readout: D[32ch x 64q] += V * Et^T (tf32; V raw fp32 -> RZ trunc).
        // All frag banks (4g+tq) bijective -> conflict-free.
        {
            const uint32_t* Eu = (const uint32_t*)Et;
            #pragma unroll
            for (int s = 0; s < 8; ++s) {
                const int k0 = s * 8;
                uint32_t a[2][4];
                #pragma unroll
                for (int i = 0; i < 2; ++i) {
                    int row = ch0 + 16 * i + g;
                    a[i][0] = VsW[row * P + k0 + tq];
                    a[i][1] = VsW[(row + 8) * P + k0 + tq];
                    a[i][2] = VsW[row * P + k0 + tq + 4];
                    a[i][3] = VsW[(row + 8) * P + k0 + tq + 4];
                }
                uint32_t bfr[8][2];
                #pragma unroll
                for (int j = 0; j < 8; ++j) {
                    int q = j * 8 + g;
                    bfr[j][0] = Eu[q * P + k0 + tq];
                    bfr[j][1] = Eu[q * P + k0 + tq + 4];
                }
                #pragma unroll
                for (int i = 0; i < 2; ++i)
                    #pragma unroll
                    for (int j = 0; j < 8; ++j)
                        mma_tf32(d[i][j], a[i], bfr[j]);
            }
        }
    }

    __syncthreads();
    if (tid < MQ) Dn[tid] = 1.0f / Dn[tid];
    __syncthreads();

    // Epilogue
    #pragma unroll
    for (int i = 0; i < 2; ++i) {
        int ch = zc + ch0 + 16 * i + g;
        float* op0 = out + ((size_t)b * CVc + ch) * NPIX + m0;
        float* op1 = out + ((size_t)b * CVc + ch + 8) * NPIX + m0;
        #pragma unroll
        for (int j = 0; j < 8; ++j) {
            int q = j * 8 + 2 * tq;
            float2 dn2 = *(const float2*)(Dn + q);
            *(float2*)(op0 + q) = make_float2(d[i][j][0] * dn2.x, d[i][j][1] * dn2.y);
            *(float2*)(op1 + q) = make_float2(d[i][j][2] * dn2.x, d[i][j][3] * dn2.y);
        }
    }
}

extern "C" void kernel_launch(void* const* d_in, const int* in_sizes, int n_in,
                              void* d_out, int out_size)
{
    const float* mk = (const float*)d_in[0];
    const float* qk = (const float*)d_in[1];
    const float* mv = (const float*)d_in[2];
    const float* qv = (const float*)d_in[3];
    float* out = (float*)d_out;

    size_t smem = (size_t)SMEM_W * sizeof(float);   // 105984 B
    cudaFuncSetAttribute(mr_attn_kernel, cudaFuncAttributeMaxDynamicSharedMemorySize, (int)smem);

    dim3 grid(NPIX / MQ, Bsz, 2);   // 49 x 16 x 2
    mr_attn_kernel<<<grid, THREADS, smem>>>(mk, qk, mv, out);

    size_t memElems = (size_t)Bsz * CVc * NPIX;
    if ((size_t)out_size >= 2 * memElems) {
        cudaMemcpyAsync(out + memElems, qv, memElems * sizeof(float),
                        cudaMemcpyDeviceToDevice);
    }
}

// round 17
// speedup vs baseline: 1.3695x; 1.3695x over previous
#include <cuda_runtime.h>
#include <cuda_bf16.h>
#include <cstdint>

// MemoryReader attention — tensor-pipe logits (bf16 3-split) + tf32 readout.
// R17 = R12 (measured best, 1666us) with EXACTLY ONE change: Q/K staging
// pitch 68 -> 72, making logit-phase fragment LDS conflict-free
// ((8tq+g) bijective; at 68 it was (4tq+g)%32 = 2-way conflicted).
// Q stays in smem (R13-R16 showed register-lifting Q causes spills/regression).
// 2 CTAs/SM via channel split; Et overlays the K region.
//   B=16, CK=64, CV=512, N=3136, 64 queries/CTA, 64-key tiles.

#define Bsz     16
#define CKc     64
#define CVc     512
#define NPIX    3136
#define MQ      64
#define NT      64
#define THREADS 256
#define NTILES  49
#define CVH     256

#define KP 72    // Q/K bf16x2 pitch: logit frag banks (8tq+g) bijective
#define P  68    // Et / V pitch: readout frag banks (4g+tq) bijective

// smem word offsets (per CTA: 26752 words = 107008 B; x2 = 214016 B <= carveout)
#define QBH_OFF 0                     // Qh [32cp][KP]
#define QBL_OFF (QBH_OFF + 32 * KP)   // Ql
#define KEH_OFF (QBL_OFF + 32 * KP)   // Kh [32cp][KP]
#define KEL_OFF (KEH_OFF + 32 * KP)   // Kl
#define ET_OFF  KEH_OFF               // Et [64q][P] tf32 — OVERLAYS Kh/Kl (4352 <= 4608)
#define VS_OFF  (KEL_OFF + 32 * KP)   // V [256ch][P] raw fp32
#define S2_OFF  (VS_OFF + CVH * P)
#define DN_OFF  (S2_OFF + NT)
#define SMEM_W  (DN_OFF + MQ)

__device__ __forceinline__ float tf32r(float x) {
    uint32_t u; asm("cvt.rna.tf32.f32 %0, %1;" : "=r"(u) : "f"(x));
    return __uint_as_float(u);
}
__device__ __forceinline__ uint32_t bf16x2p(float odd, float even) {
    uint32_t r;
    asm("cvt.rn.bf16x2.f32 %0, %1, %2;" : "=r"(r) : "f"(odd), "f"(even));
    return r;
}
__device__ __forceinline__ float bfLO(uint32_t w) { return __uint_as_float(w << 16); }
__device__ __forceinline__ float bfHI(uint32_t w) { return __uint_as_float(w & 0xffff0000u); }

__device__ __forceinline__ void mma_tf32(float d[4], const uint32_t a[4], const uint32_t b[2]) {
    asm volatile(
        "mma.sync.aligned.m16n8k8.row.col.f32.tf32.tf32.f32 "
        "{%0,%1,%2,%3}, {%4,%5,%6,%7}, {%8,%9}, {%0,%1,%2,%3};"
        : "+f"(d[0]), "+f"(d[1]), "+f"(d[2]), "+f"(d[3])
        : "r"(a[0]), "r"(a[1]), "r"(a[2]), "r"(a[3]), "r"(b[0]), "r"(b[1]));
}
__device__ __forceinline__ void mma_bf16(float d[4], const uint32_t a[4], const uint32_t b[2]) {
    asm volatile(
        "mma.sync.aligned.m16n8k16.row.col.f32.bf16.bf16.f32 "
        "{%0,%1,%2,%3}, {%4,%5,%6,%7}, {%8,%9}, {%0,%1,%2,%3};"
        : "+f"(d[0]), "+f"(d[1]), "+f"(d[2]), "+f"(d[3])
        : "r"(a[0]), "r"(a[1]), "r"(a[2]), "r"(a[3]), "r"(b[0]), "r"(b[1]));
}
__device__ __forceinline__ void cpasync16(uint32_t dst, const void* src) {
    asm volatile("cp.async.cg.shared.global [%0], [%1], 16;" :: "r"(dst), "l"(src));
}

__global__ __launch_bounds__(THREADS, 2)
void mr_attn_kernel(const float* __restrict__ mk, const float* __restrict__ qk,
                    const float* __restrict__ mv, float* __restrict__ out)
{
    extern __shared__ float sm[];
    float* Et = sm + ET_OFF;
    float* S2 = sm + S2_OFF;
    float* Dn = sm + DN_OFF;
    uint32_t* Qh = (uint32_t*)(sm + QBH_OFF);
    uint32_t* Ql = (uint32_t*)(sm + QBL_OFF);
    uint32_t* Kh = (uint32_t*)(sm + KEH_OFF);
    uint32_t* Kl = (uint32_t*)(sm + KEL_OFF);
    uint32_t* VsW = (uint32_t*)(sm + VS_OFF);

    uint32_t sbase;
    asm("{ .reg .u64 t; cvta.to.shared.u64 t, %1; cvt.u32.u64 %0, t; }"
        : "=r"(sbase) : "l"(sm));

    const int b    = blockIdx.y;
    const int m0   = blockIdx.x * MQ;
    const int zc   = blockIdx.z * CVH;
    const int tid  = threadIdx.x;
    const int wid  = tid >> 5;
    const int lane = tid & 31;
    const int g    = lane >> 2;
    const int tq   = lane & 3;

    const float* qb = qk + (size_t)b * CKc * NPIX + m0;
    const float* kb = mk + (size_t)b * CKc * NPIX;
    const float* vb = mv + ((size_t)b * CVc + zc) * NPIX;

    // Build Qb hi/lo bf16x2 ONCE (512 slots, 2 iters); pitch KP
    #pragma unroll
    for (int it = 0; it < 2; ++it) {
        int slot = it * THREADS + tid;
        int cp = slot >> 4, m4 = slot & 15;
        const float* q0p = qb + (2 * cp) * NPIX + 4 * m4;
        float4 qe = *(const float4*)(q0p);
        float4 qo = *(const float4*)(q0p + NPIX);
        float xe[4] = {qe.x, qe.y, qe.z, qe.w};
        float xo[4] = {qo.x, qo.y, qo.z, qo.w};
        uint32_t hv[4], lv[4];
        #pragma unroll
        for (int r = 0; r < 4; ++r) {
            uint32_t h = bf16x2p(xo[r], xe[r]);
            hv[r] = h;
            lv[r] = bf16x2p(xo[r] - bfHI(h), xe[r] - bfLO(h));
        }
        *(uint4*)(Qh + cp * KP + 4 * m4) = *(uint4*)hv;
        *(uint4*)(Ql + cp * KP + 4 * m4) = *(uint4*)lv;
    }
    if (tid < MQ) Dn[tid] = 0.f;

    // Readout accumulators: warp slab 32ch x 64q
    float d[2][8][4];
    #pragma unroll
    for (int i = 0; i < 2; ++i)
        #pragma unroll
        for (int j = 0; j < 8; ++j)
            #pragma unroll
            for (int r = 0; r < 4; ++r) d[i][j][r] = 0.f;

    const int ch0 = wid * 32;        // readout channel slab (within CTA half)
    const int wq  = wid & 3;         // logit q m-tile (16q)
    const int wk  = wid >> 2;        // logit k half (32k)
    const int q0  = wq * 16;
    const int kh0 = wk * 32;

    for (int t = 0; t < NTILES; ++t) {
        const int n0 = t * NT;
        __syncthreads();   // prev readout done; V/K(Et) reusable (Q stores at t=0)

        // V tile: cp.async raw fp32 (overlaps logit phase)
        #pragma unroll
        for (int i = 0; i < 16; ++i) {
            int idx = i * THREADS + tid;
            int c = idx >> 4, n4 = idx & 15;
            cpasync16(sbase + (uint32_t)(VS_OFF + c * P + 4 * n4) * 4u,
                      vb + c * NPIX + n0 + 4 * n4);
        }
        asm volatile("cp.async.commit_group;" ::: "memory");

        // K tile -> bf16 hi/lo packed cpairs (512 slots, 2 iters); pitch KP
        #pragma unroll
        for (int it = 0; it < 2; ++it) {
            int slot = it * THREADS + tid;
            int cp = slot >> 4, n4 = slot & 15;
            const float* k0p = kb + (2 * cp) * NPIX + n0 + 4 * n4;
            float4 ke = *(const float4*)(k0p);
            float4 ko = *(const float4*)(k0p + NPIX);
            float xe[4] = {ke.x, ke.y, ke.z, ke.w};
            float xo[4] = {ko.x, ko.y, ko.z, ko.w};
            uint32_t hv[4], lv[4];
            #pragma unroll
            for (int r = 0; r < 4; ++r) {
                uint32_t h = bf16x2p(xo[r], xe[r]);
                hv[r] = h;
                lv[r] = bf16x2p(xo[r] - bfHI(h), xe[r] - bfLO(h));
            }
            *(uint4*)(Kh + cp * KP + 4 * n4) = *(uint4*)hv;
            *(uint4*)(Kl + cp * KP + 4 * n4) = *(uint4*)lv;
        }
        __syncthreads();   // Kb ready

        // ||k||^2 (warps 0-1); banks (8cp+lane) conflict-free
        if (tid < NT) {
            float s = 0.f;
            #pragma unroll
            for (int cp = 0; cp < 32; ++cp) {
                uint32_t wh = Kh[cp * KP + tid], wl = Kl[cp * KP + tid];
                float ke = bfLO(wh) + bfLO(wl);
                float ko = bfHI(wh) + bfHI(wl);
                s = fmaf(ke, ke, fmaf(ko, ko, s));
            }
            S2[tid] = s;
        }

        // Logit MMA: warp = 16q x 32k, 3x bf16-split, 4 csteps of k16.
        // Frag banks (8tq+g) bijective -> conflict-free (the R17 fix).
        float dl[4][4];
        #pragma unroll
        for (int j = 0; j < 4; ++j)
            #pragma unroll
            for (int r = 0; r < 4; ++r) dl[j][r] = 0.f;
        #pragma unroll
        for (int cs = 0; cs < 4; ++cs) {
            const int cb = cs * 8;
            uint32_t ah[4], al[4];
            ah[0] = Qh[(cb + tq) * KP + q0 + g];
            ah[1] = Qh[(cb + tq) * KP + q0 + g + 8];
            ah[2] = Qh[(cb + tq + 4) * KP + q0 + g];
            ah[3] = Qh[(cb + tq + 4) * KP + q0 + g + 8];
            al[0] = Ql[(cb + tq) * KP + q0 + g];
            al[1] = Ql[(cb + tq) * KP + q0 + g + 8];
            al[2] = Ql[(cb + tq + 4) * KP + q0 + g];
            al[3] = Ql[(cb + tq + 4) * KP + q0 + g + 8];
            #pragma unroll
            for (int j = 0; j < 4; ++j) {
                const int kk0 = kh0 + 8 * j;
                uint32_t bh[2], bl2[2];
                bh[0]  = Kh[(cb + tq) * KP + kk0 + g];
                bh[1]  = Kh[(cb + tq + 4) * KP + kk0 + g];
                bl2[0] = Kl[(cb + tq) * KP + kk0 + g];
                bl2[1] = Kl[(cb + tq + 4) * KP + kk0 + g];
                mma_bf16(dl[j], ah, bh);
                mma_bf16(dl[j], ah, bl2);
                mma_bf16(dl[j], al, bh);
            }
        }
        __syncthreads();   // all K reads done (S2 + logit) -> Et may overlay

        // exp + Et[q][k] (tf32 bits, OVERLAYS K region) + denominator
        {
            const float C1 = 0.125f * 1.4426950408889634f;   // log2(e)/8
            float pA = 0.f, pB = 0.f;
            #pragma unroll
            for (int j = 0; j < 4; ++j) {
                const int kk = kh0 + 8 * j + 2 * tq;
                float2 s2v = *(const float2*)(S2 + kk);
                float sbx = s2v.x * C1, sby = s2v.y * C1;
                float e0 = exp2f(fmaf(dl[j][0], 2.f * C1, -sbx));
                float e1 = exp2f(fmaf(dl[j][1], 2.f * C1, -sby));
                float e2 = exp2f(fmaf(dl[j][2], 2.f * C1, -sbx));
                float e3 = exp2f(fmaf(dl[j][3], 2.f * C1, -sby));
                *(float2*)(Et + (q0 + g) * P + kk)     = make_float2(tf32r(e0), tf32r(e1));
                *(float2*)(Et + (q0 + g + 8) * P + kk) = make_float2(tf32r(e2), tf32r(e3));
                pA += e0 + e1;
                pB += e2 + e3;
            }
            pA += __shfl_xor_sync(0xffffffffu, pA, 1);
            pA += __shfl_xor_sync(0xffffffffu, pA, 2);
            pB += __shfl_xor_sync(0xffffffffu, pB, 1);
            pB += __shfl_xor_sync(0xffffffffu, pB, 2);
            if (tq == 0) {
                atomicAdd(&Dn[q0 + g], pA);
                atomicAdd(&Dn[q0 + g + 8], pB);
            }
        }
        asm volatile("cp.async.wait_group 0;" ::: "memory");
        __syncthreads();   // Et + Vs ready

        // Readout MMA: D[32ch x 64q] += V * Et^T (tf32; V raw fp32 RZ-truncated)
        {
            const uint32_t* Eu = (const uint32_t*)Et;
            #pragma unroll
            for (int s = 0; s < 8; ++s) {
                const int k0 = s * 8;
                uint32_t a[2][4];
                #pragma unroll
                for (int i = 0; i < 2; ++i) {
                    int row = ch0 + 16 * i + g;
                    a[i][0] = VsW[row * P + k0 + tq];
                    a[i][1] = VsW[(row + 8) * P + k0 + tq];
                    a[i][2] = VsW[row * P + k0 + tq + 4];
                    a[i][3] = VsW[(row + 8) * P + k0 + tq + 4];
                }
                uint32_t bfr[8][2];
                #pragma unroll
                for (int j = 0; j < 8; ++j) {
                    int q = j * 8 + g;
                    bfr[j][0] = Eu[q * P + k0 + tq];
                    bfr[j][1] = Eu[q * P + k0 + tq + 4];
                }
                #pragma unroll
                for (int i = 0; i < 2; ++i)
                    #pragma unroll
                    for (int j = 0; j < 8; ++j)
                        mma_tf32(d[i][j], a[i], bfr[j]);
            }
        }
    }
    __syncthreads();
    if (tid < MQ) Dn[tid] = 1.0f / Dn[tid];
    __syncthreads();

    // Epilogue
    #pragma unroll
    for (int i = 0; i < 2; ++i) {
        int ch = zc + ch0 + 16 * i + g;
        float* op0 = out + ((size_t)b * CVc + ch) * NPIX + m0;
        float* op1 = out + ((size_t)b * CVc + ch + 8) * NPIX + m0;
        #pragma unroll
        for (int j = 0; j < 8; ++j) {
            int q = j * 8 + 2 * tq;
            float2 dn2 = *(const float2*)(Dn + q);
            *(float2*)(op0 + q) = make_float2(d[i][j][0] * dn2.x, d[i][j][1] * dn2.y);
            *(float2*)(op1 + q) = make_float2(d[i][j][2] * dn2.x, d[i][j][3] * dn2.y);
        }
    }
}

extern "C" void kernel_launch(void* const* d_in, const int* in_sizes, int n_in,
                              void* d_out, int out_size)
{
    const float* mk = (const float*)d_in[0];
    const float* qk = (const float*)d_in[1];
    const float* mv = (const float*)d_in[2];
    const float* qv = (const float*)d_in[3];
    float* out = (float*)d_out;

    size_t smem = (size_t)SMEM_W * sizeof(float);   // 107008 B
    cudaFuncSetAttribute(mr_attn_kernel, cudaFuncAttributeMaxDynamicSharedMemorySize, (int)smem);

    dim3 grid(NPIX / MQ, Bsz, 2);   // 49 x 16 x 2 (channel halves)
    mr_attn_kernel<<<grid, THREADS, smem>>>(mk, qk, mv, out);

    size_t memElems = (size_t)Bsz * CVc * NPIX;
    if ((size_t)out_size >= 2 * memElems) {
        cudaMemcpyAsync(out + memElems, qv, memElems * sizeof(float),
                        cudaMemcpyDeviceToDevice);
    }
}